// round 8
// baseline (speedup 1.0000x reference)
#include <cuda_runtime.h>

// SpatialTransformer 3D trilinear resample. B=4, H=W=D=128, C=2, fp32.
//
// R5: R4's tile-transposed + software-pipelined structure, plus x-corner-pair
// merge: (pa@x0, pc@x1) fetched as ONE aligned LDG.128 at xe=x0&~1 covering
// [xe, xe+1], with a predicated LDG.64 extra only for (x0 odd && dx==1) lanes.
// Cuts gather wavefronts ~30%. Stage stores only (px,py,pz); weights and
// selection flags recomputed in the math phase to contain registers.
//
// Reference conventions reproduced exactly: full-extent pixel mapping,
// clip-then-float corners, flat index y*W + z*W*H + x, far-slab weight
// (z1f - z0f).

#define HH 128
#define WW 128
#define DD 128
#define NPB (HH * WW * DD)      // 2097152

struct Stage {
    float4 q00, q10, q01, q11;   // [xe, xe+1] windows for the 4 (y,z) corners
    float2 e00, e10, e01, e11;   // predicated extras at x0+1 (odd && dx)
    float  px, py, pz;
    int    kl;
};

__device__ __forceinline__ void stage_load(
    const float2* __restrict__ im2,
    float t2, float t6, float t10,
    float cx, float cy, float cz,
    int k0, int kl, Stage& sg)
{
    sg.kl = kl;
    const float s = 2.0f / 127.0f;
    const float zg = fmaf((float)(k0 + kl), s, -1.0f);

    const float px = (fmaf(t2,  zg, cx) + 1.0f) * 64.0f;
    const float py = (fmaf(t6,  zg, cy) + 1.0f) * 64.0f;
    const float pz = (fmaf(t10, zg, cz) + 1.0f) * 64.0f;
    sg.px = px; sg.py = py; sg.pz = pz;

    const int fx = __float2int_rd(px);
    const int fy = __float2int_rd(py);
    const int fz = __float2int_rd(pz);

    const int x0 = min(max(fx,     0), WW - 1);
    const int x1 = min(max(fx + 1, 0), WW - 1);
    const int y0 = min(max(fy,     0), HH - 1);
    const int y1 = min(max(fy + 1, 0), HH - 1);
    const int z0 = min(max(fz,     0), DD - 1);
    const int z1 = min(max(fz + 1, 0), DD - 1);

    // reference flat convention: y*W + z*(W*H) + x
    const int r00 = y0 * WW + z0 * (WW * HH);
    const int dy  = (y1 - y0) * WW;
    const int dz  = (z1 - z0) * (WW * HH);

    const int xe = x0 & ~1;                 // 16B-aligned window start
    const float4* b00 = (const float4*)(im2 + r00 + xe);
    const float4* b10 = (const float4*)(im2 + r00 + dy + xe);
    const float4* b01 = (const float4*)(im2 + r00 + dz + xe);
    const float4* b11 = (const float4*)(im2 + r00 + dy + dz + xe);
    sg.q00 = __ldg(b00);
    sg.q10 = __ldg(b10);
    sg.q01 = __ldg(b01);
    sg.q11 = __ldg(b11);

    const bool need_extra = (x0 & 1) && (x1 != x0);
    if (need_extra) {
        const int xp = x0 + 1;
        sg.e00 = __ldg(im2 + r00 + xp);
        sg.e10 = __ldg(im2 + r00 + dy + xp);
        sg.e01 = __ldg(im2 + r00 + dz + xp);
        sg.e11 = __ldg(im2 + r00 + dy + dz + xp);
    }
}

__device__ __forceinline__ float2 stage_math(const Stage& sg)
{
    const float px = sg.px, py = sg.py, pz = sg.pz;

    const float fxf = floorf(px);
    const float fyf = floorf(py);
    const float fzf = floorf(pz);

    const float x0f = fminf(fmaxf(fxf,        0.0f), 127.0f);
    const float x1f = fminf(fmaxf(fxf + 1.0f, 0.0f), 127.0f);
    const float y0f = fminf(fmaxf(fyf,        0.0f), 127.0f);
    const float y1f = fminf(fmaxf(fyf + 1.0f, 0.0f), 127.0f);
    const float z0f = fminf(fmaxf(fzf,        0.0f), 127.0f);
    const float z1f = fminf(fmaxf(fzf + 1.0f, 0.0f), 127.0f);

    const int  x0   = (int)x0f;
    const bool odd  = (x0 & 1);
    const bool dx   = (x1f != x0f);
    const bool nx   = odd && dx;
    const bool hi_c = odd || dx;            // pc from q.hi unless even && !dx

    // pa: odd ? hi : lo ;  pc: nx ? extra : (hi_c ? hi : lo)
    float2 pa, pc, pb, pd, pe, pg, pf, ph;
    pa.x = odd ? sg.q00.z : sg.q00.x;  pa.y = odd ? sg.q00.w : sg.q00.y;
    pb.x = odd ? sg.q10.z : sg.q10.x;  pb.y = odd ? sg.q10.w : sg.q10.y;
    pe.x = odd ? sg.q01.z : sg.q01.x;  pe.y = odd ? sg.q01.w : sg.q01.y;
    pf.x = odd ? sg.q11.z : sg.q11.x;  pf.y = odd ? sg.q11.w : sg.q11.y;

    pc.x = nx ? sg.e00.x : (hi_c ? sg.q00.z : sg.q00.x);
    pc.y = nx ? sg.e00.y : (hi_c ? sg.q00.w : sg.q00.y);
    pd.x = nx ? sg.e10.x : (hi_c ? sg.q10.z : sg.q10.x);
    pd.y = nx ? sg.e10.y : (hi_c ? sg.q10.w : sg.q10.y);
    pg.x = nx ? sg.e01.x : (hi_c ? sg.q01.z : sg.q01.x);
    pg.y = nx ? sg.e01.y : (hi_c ? sg.q01.w : sg.q01.y);
    ph.x = nx ? sg.e11.x : (hi_c ? sg.q11.z : sg.q11.x);
    ph.y = nx ? sg.e11.y : (hi_c ? sg.q11.w : sg.q11.y);

    const float wx1 = x1f - px, wx0 = px - x0f;
    const float wy1 = y1f - py, wy0 = py - y0f;
    const float wzA = z1f - pz;              // near slab (z1f - z)
    const float wzB = z1f - z0f;             // far slab  (z1f - z0f) — ref convention

    float2 r;
    r.x = wzA * (wy1 * fmaf(wx1, pa.x, wx0 * pc.x) + wy0 * fmaf(wx1, pb.x, wx0 * pd.x))
        + wzB * (wy1 * fmaf(wx1, pe.x, wx0 * pg.x) + wy0 * fmaf(wx1, pf.x, wx0 * ph.x));
    r.y = wzA * (wy1 * fmaf(wx1, pa.y, wx0 * pc.y) + wy0 * fmaf(wx1, pb.y, wx0 * pd.y))
        + wzB * (wy1 * fmaf(wx1, pe.y, wx0 * pg.y) + wy0 * fmaf(wx1, pf.y, wx0 * ph.y));
    return r;
}

__global__ __launch_bounds__(256, 3) void st3d_kernel(
    const float* __restrict__ image,   // [B, H, W, D, C] flat, C=2
    const float* __restrict__ theta,   // [B, 3, 4]
    float2* __restrict__ out)          // [B*N] float2
{
    __shared__ float2 tile[32][33];

    const int tid  = threadIdx.x;
    const int lane = tid & 31;
    const int wid  = tid >> 5;

    // grid: 4 k-tiles * 4 j-tiles * 128 i * 4 b = 8192 blocks
    const unsigned bx = blockIdx.x;
    const int k0 = (bx & 3) << 5;
    const int j0 = ((bx >> 2) & 3) << 5;
    const int i  = (bx >> 4) & 127;
    const int b  = bx >> 11;

    const float* t = theta + b * 12;
    const float t0  = __ldg(t + 0),  t1  = __ldg(t + 1),  t2  = __ldg(t + 2),  t3  = __ldg(t + 3);
    const float t4  = __ldg(t + 4),  t5  = __ldg(t + 5),  t6  = __ldg(t + 6),  t7  = __ldg(t + 7);
    const float t8  = __ldg(t + 8),  t9  = __ldg(t + 9),  t10 = __ldg(t + 10), t11 = __ldg(t + 11);

    const float s = 2.0f / 127.0f;
    const int j = j0 + lane;                       // lane varies x
    const float xg = fmaf((float)j, s, -1.0f);
    const float yg = fmaf((float)i, s, -1.0f);

    const float cx = fmaf(t0, xg, fmaf(t1, yg, t3));
    const float cy = fmaf(t4, xg, fmaf(t5, yg, t7));
    const float cz = fmaf(t8, xg, fmaf(t9, yg, t11));

    const float2* __restrict__ im2 = (const float2*)image + (size_t)b * NPB;

    // 2-deep software pipeline over the 4 k-iterations (kl = wid + 8*it)
    Stage s0, s1;
    stage_load(im2, t2, t6, t10, cx, cy, cz, k0, wid,      s0);
    stage_load(im2, t2, t6, t10, cx, cy, cz, k0, wid + 8,  s1);

    tile[lane][s0.kl] = stage_math(s0);
    stage_load(im2, t2, t6, t10, cx, cy, cz, k0, wid + 16, s0);

    tile[lane][s1.kl] = stage_math(s1);
    stage_load(im2, t2, t6, t10, cx, cy, cz, k0, wid + 24, s1);

    tile[lane][s0.kl] = stage_math(s0);
    tile[lane][s1.kl] = stage_math(s1);

    __syncthreads();

    // store phase: lane varies k -> coalesced 256B warp stores
    float2* __restrict__ op = out + (size_t)b * NPB + i * (WW * DD) + j0 * DD + k0;
    #pragma unroll
    for (int it = 0; it < 4; it++) {
        const int jl = wid + 8 * it;
        op[jl * DD + lane] = tile[jl][lane];
    }
}

extern "C" void kernel_launch(void* const* d_in, const int* in_sizes, int n_in,
                              void* d_out, int out_size) {
    const float* image = (const float*)d_in[0];
    const float* theta = (const float*)d_in[1];
    float2* out = (float2*)d_out;

    st3d_kernel<<<8192, 256>>>(image, theta, out);
}